// round 4
// baseline (speedup 1.0000x reference)
#include <cuda_runtime.h>

#define DIM   1024
#define BATCH 64
#define LOG2E 1.44269504f

// ---- scratch (device globals: no allocations allowed) ----
__device__ float g_qp[BATCH * DIM];
__device__ float g_kp[BATCH * DIM];
__device__ float g_g2[BATCH * DIM];
__device__ float g_w1s[DIM];

__device__ __forceinline__ float ex2f_(float x) {
    float y; asm("ex2.approx.ftz.f32 %0, %1;" : "=f"(y) : "f"(x)); return y;
}
__device__ __forceinline__ float rcpf_(float x) {
    float y; asm("rcp.approx.ftz.f32 %0, %1;" : "=f"(y) : "f"(x)); return y;
}
__device__ __forceinline__ float tanhf_(float x) {
    float y; asm("tanh.approx.f32 %0, %1;" : "=f"(y) : "f"(x)); return y;
}

// ---------------------------------------------------------------------------
// Dot-product GEMM: out[m, n] = sum_k A[m,k] * W[n*ldw + k] + bias[n]
// Warp tile 4m x 4n (16 accs), block = 8 warps -> 8m x 16n.
// 512 blocks per 64x1024 output. Lane owns k = kc*128 + lane*4 (K=1024).
// Small tile keeps regs ~64 so 3 blocks/SM hide the DRAM latency chain.
// ---------------------------------------------------------------------------
__device__ __forceinline__ void gemm_dot(const float* __restrict__ A,
                                         const float* __restrict__ W, int ldw,
                                         const float* __restrict__ bias,
                                         float* __restrict__ out, int bb)
{
    int warp = threadIdx.x >> 5, lane = threadIdx.x & 31;
    int m0 = (bb & 7) * 8 + (warp & 1) * 4;
    int n0 = (bb >> 3) * 16 + (warp >> 1) * 4;

    float v[16];
    #pragma unroll
    for (int t = 0; t < 16; t++) v[t] = 0.f;

    const float* ap = A + (size_t)m0 * DIM + lane * 4;
    const float* wp = W + (size_t)n0 * ldw + lane * 4;

    #pragma unroll 1
    for (int kc = 0; kc < 8; kc++) {
        float4 a[4], b[4];
        #pragma unroll
        for (int i = 0; i < 4; i++)
            a[i] = *(const float4*)(ap + (size_t)i * DIM + kc * 128);
        #pragma unroll
        for (int j = 0; j < 4; j++)
            b[j] = *(const float4*)(wp + (size_t)j * ldw + kc * 128);
        #pragma unroll
        for (int i = 0; i < 4; i++)
            #pragma unroll
            for (int j = 0; j < 4; j++) {
                float s = v[i * 4 + j];
                s = fmaf(a[i].x, b[j].x, s);
                s = fmaf(a[i].y, b[j].y, s);
                s = fmaf(a[i].z, b[j].z, s);
                s = fmaf(a[i].w, b[j].w, s);
                v[i * 4 + j] = s;
            }
    }

    // fold upper half-warp, then 16-lane transpose-reduce: lane L (<16) ends
    // holding the full sum for value index L (i = L>>2 -> m, j = L&3 -> n)
    #pragma unroll
    for (int i = 0; i < 16; i++)
        v[i] += __shfl_xor_sync(0xffffffffu, v[i], 16);
    int l4 = lane & 15;
    #pragma unroll
    for (int s = 8; s; s >>= 1) {
        bool hi = (l4 & s) != 0;
        #pragma unroll
        for (int i = 0; i < 8; i++) {
            if (i < s) {
                float send = hi ? v[i] : v[i + s];
                float recv = __shfl_xor_sync(0xffffffffu, send, s);
                v[i] = (hi ? v[i + s] : v[i]) + recv;
            }
        }
    }
    if (lane < 16) {
        int m = m0 + (lane >> 2), n = n0 + (lane & 3);
        out[(size_t)m * DIM + n] = v[0] + bias[n];
    }
}

// ---------------------------------------------------------------------------
// Phase 1: k_proj (512) + q_proj (512) + w1_row_sum (16)  = 1040 blocks
// ---------------------------------------------------------------------------
__global__ __launch_bounds__(256, 3) void phase1_kernel(
    const float* __restrict__ q, const float* __restrict__ Wq,
    const float* __restrict__ bq,
    const float* __restrict__ k, const float* __restrict__ Wk,
    const float* __restrict__ bk, const float* __restrict__ Wg)
{
    int bb = blockIdx.x;
    if (bb < 512) {
        gemm_dot(k, Wk, DIM, bk, g_kp, bb);
    } else if (bb < 1024) {
        gemm_dot(q, Wq, DIM, bq, g_qp, bb - 512);
    } else {
        int warp = threadIdx.x >> 5, lane = threadIdx.x & 31;
        int base = (bb - 1024) * 64;
        #pragma unroll
        for (int it = 0; it < 8; it++) {
            int row = base + it * 8 + warp;
            const float* p = Wg + (size_t)row * (2 * DIM);
            float s = 0.f;
            #pragma unroll 8
            for (int t = 0; t < DIM / 32; t++) s += p[lane + 32 * t];
            #pragma unroll
            for (int o = 16; o > 0; o >>= 1) s += __shfl_xor_sync(0xffffffffu, s, o);
            if (lane == 0) g_w1s[row] = s;
        }
    }
}

// ---------------------------------------------------------------------------
// Phase 2: g2 = kp @ W2.T + bg   (kp hot in L2)  512 blocks
// ---------------------------------------------------------------------------
__global__ __launch_bounds__(256, 3) void phase2_kernel(
    const float* __restrict__ Wg, const float* __restrict__ bg)
{
    gemm_dot(g_kp, Wg + DIM, 2 * DIM, bg, g_g2, blockIdx.x);
}

// ---------------------------------------------------------------------------
// Fused gate + scores + softmax.
// grid (32, 64): blockIdx.y = batch, blockIdx.x = 32-row i-tile.
// 256 threads = 4 groups of 64 lanes; each group owns a row (2 warps/row),
// 16 j-elements per lane in registers; kp/g2/w1s register-resident.
// sigmoid(x) = 0.5 + 0.5*tanh(x/2). Outer sigmoid: MUFU tanh.
// Inner sigmoid: tanh(v), v = s1/2 in (0, 0.5) -> degree-7 odd polynomial
// (max abs err 3.8e-5), so only 2 MUFU/elem (tanh + ex2).
// No max-subtraction: |score*gate| <~ 5, fp32-safe.
// ---------------------------------------------------------------------------
__device__ __forceinline__ float elem_(float qp, float w1s_h, float g2_h,
                                       float kp_sh, float& sum)
{
    float qkh = qp * kp_sh;                      // 0.5*log2e*score
    float gph = fmaf(qp, w1s_h, g2_h);           // 0.5*gate_pre
    float t1  = tanhf_(gph);                     // tanh(gate_pre/2)
    float v   = fmaf(0.25f, t1, 0.25f);          // s1/2 in (0, 0.5)
    float w   = v * v;
    float p   = fmaf(-0.05396825f, w, 0.13333333f);   // -17/315, 2/15
    p = fmaf(p, w, -0.33333333f);
    p = fmaf(p, w, 1.0f);
    float t2  = v * p;                           // tanh(s1/2)
    float e   = ex2f_(fmaf(qkh, t2, qkh));       // exp2(log2e*score*gate)
    sum += e;
    return e;
}

__global__ __launch_bounds__(256) void attn_kernel(float* __restrict__ out)
{
    int tid   = threadIdx.x;
    int group = tid >> 6;      // 0..3
    int gl    = tid & 63;      // lane within 64-lane group
    int warp  = tid >> 5;      // 0..7
    int lane  = tid & 31;
    int b     = blockIdx.y;

    const float4* kp4  = (const float4*)(g_kp + (size_t)b * DIM);
    const float4* g24  = (const float4*)(g_g2 + (size_t)b * DIM);
    const float4* w1s4 = (const float4*)g_w1s;

    const float KS = 0.5f * LOG2E;
    float4 kps[4], g2s[4], w1ss[4];
    #pragma unroll
    for (int t = 0; t < 4; t++) {
        int idx = t * 64 + gl;
        float4 kv = kp4[idx];
        kps[t].x = kv.x * KS;   kps[t].y = kv.y * KS;
        kps[t].z = kv.z * KS;   kps[t].w = kv.w * KS;
        float4 gv = g24[idx];
        g2s[t].x = gv.x * 0.5f; g2s[t].y = gv.y * 0.5f;
        g2s[t].z = gv.z * 0.5f; g2s[t].w = gv.w * 0.5f;
        float4 wv = w1s4[idx];
        w1ss[t].x = wv.x * 0.5f; w1ss[t].y = wv.y * 0.5f;
        w1ss[t].z = wv.z * 0.5f; w1ss[t].w = wv.w * 0.5f;
    }

    __shared__ float s_part[2][8];

    const float* qp_row = g_qp + (size_t)b * DIM;
    int i0 = blockIdx.x * 32 + group;

    for (int r = 0; r < 8; r++) {
        int i = i0 + r * 4;
        float qp = __ldg(qp_row + i);
        float sum = 0.f;
        float4 ev[4];
        #pragma unroll
        for (int t = 0; t < 4; t++) {
            ev[t].x = elem_(qp, w1ss[t].x, g2s[t].x, kps[t].x, sum);
            ev[t].y = elem_(qp, w1ss[t].y, g2s[t].y, kps[t].y, sum);
            ev[t].z = elem_(qp, w1ss[t].z, g2s[t].z, kps[t].z, sum);
            ev[t].w = elem_(qp, w1ss[t].w, g2s[t].w, kps[t].w, sum);
        }
        #pragma unroll
        for (int o = 16; o > 0; o >>= 1) sum += __shfl_xor_sync(0xffffffffu, sum, o);
        if (lane == 0) s_part[r & 1][warp] = sum;
        __syncthreads();
        float tot  = s_part[r & 1][group * 2] + s_part[r & 1][group * 2 + 1];
        float rinv = rcpf_(tot);

        float4* o4 = (float4*)out + (size_t)(b * DIM + i) * (DIM / 4);
        #pragma unroll
        for (int t = 0; t < 4; t++) {
            float4 o;
            o.x = ev[t].x * rinv; o.y = ev[t].y * rinv;
            o.z = ev[t].z * rinv; o.w = ev[t].w * rinv;
            __stcs(&o4[t * 64 + gl], o);
        }
    }
}

// ---------------------------------------------------------------------------
extern "C" void kernel_launch(void* const* d_in, const int* in_sizes, int n_in,
                              void* d_out, int out_size)
{
    const float* q  = (const float*)d_in[0];
    const float* k  = (const float*)d_in[1];
    // d_in[2] = v : unused by the reference math
    const float* Wq = (const float*)d_in[3];
    const float* bq = (const float*)d_in[4];
    const float* Wk = (const float*)d_in[5];
    const float* bk = (const float*)d_in[6];
    const float* Wg = (const float*)d_in[7];
    const float* bg = (const float*)d_in[8];
    float* out = (float*)d_out;

    phase1_kernel<<<1040, 256>>>(q, Wq, bq, k, Wk, bk, Wg);
    phase2_kernel<<<512, 256>>>(Wg, bg);
    attn_kernel  <<<dim3(32, 64), 256>>>(out);
}

// round 14
// speedup vs baseline: 1.0295x; 1.0295x over previous
#include <cuda_runtime.h>

#define DIM    1024
#define BATCH  64
#define LOG2E  1.44269504f
#define SPLITS 8            // K split per GEMM
#define KSEG   (DIM / SPLITS)   // 128 k per block
#define KC     16           // k per smem chunk
#define NC     (KSEG / KC)  // 8 chunks

// ---- scratch (device globals: no allocations allowed) ----
__device__ __align__(16) float g_qp_part[SPLITS][BATCH * DIM];
__device__ __align__(16) float g_kp_part[SPLITS][BATCH * DIM];
__device__ __align__(16) float g_g2_part[SPLITS][BATCH * DIM];
__device__ __align__(16) float g_qp[BATCH * DIM];   // final, bias folded
__device__ __align__(16) float g_kp[BATCH * DIM];   // final, bias folded
__device__ __align__(16) float g_w1s[DIM];

__device__ __forceinline__ float ex2f_(float x) {
    float y; asm("ex2.approx.ftz.f32 %0, %1;" : "=f"(y) : "f"(x)); return y;
}
__device__ __forceinline__ float rcpf_(float x) {
    float y; asm("rcp.approx.ftz.f32 %0, %1;" : "=f"(y) : "f"(x)); return y;
}
__device__ __forceinline__ float tanhf_(float x) {
    float y; asm("tanh.approx.f32 %0, %1;" : "=f"(y) : "f"(x)); return y;
}

// ---------------------------------------------------------------------------
// Split-K smem-tiled GEMM partial:
//   outp[m, ntile*64 + n] = sum_{k in split's 128-k segment} A[m,k] * W[n_g*ldw + k]
// Block: 256 threads, tile 64m x 64n x 128k. Thread tile 4m x 4n.
// Double-buffered smem chunks of 16 k; As/Ws stored [k][m]/[k][n] (padded 68)
// so inner LDS.128 reads are conflict-free broadcasts.
// ---------------------------------------------------------------------------
__device__ __forceinline__ void gemm_split(const float* __restrict__ A,
                                           const float* __restrict__ W, int ldw,
                                           float* __restrict__ outp,
                                           int ntile, int split)
{
    __shared__ float As[2][KC][68];
    __shared__ float Ws[2][KC][68];

    int tid = threadIdx.x;
    int ty = tid >> 4, tx = tid & 15;       // compute mapping
    int m0 = ty * 4,   n0 = tx * 4;
    int lm = tid >> 2, lk = (tid & 3) * 4;  // load mapping: row lm, k-offset lk

    int kbase = split * KSEG;
    const float* aptr = A + (size_t)lm * DIM + kbase + lk;
    const float* wptr = W + (size_t)(ntile * 64 + lm) * ldw + kbase + lk;

    float4 ra = *(const float4*)aptr;
    float4 rw = *(const float4*)wptr;

    // store chunk 0
    As[0][lk + 0][lm] = ra.x; As[0][lk + 1][lm] = ra.y;
    As[0][lk + 2][lm] = ra.z; As[0][lk + 3][lm] = ra.w;
    Ws[0][lk + 0][lm] = rw.x; Ws[0][lk + 1][lm] = rw.y;
    Ws[0][lk + 2][lm] = rw.z; Ws[0][lk + 3][lm] = rw.w;
    __syncthreads();

    float acc[4][4];
    #pragma unroll
    for (int i = 0; i < 4; i++)
        #pragma unroll
        for (int j = 0; j < 4; j++) acc[i][j] = 0.f;

    #pragma unroll 1
    for (int c = 0; c < NC; c++) {
        int buf = c & 1;
        if (c + 1 < NC) {                       // prefetch next chunk early
            ra = *(const float4*)(aptr + (c + 1) * KC);
            rw = *(const float4*)(wptr + (c + 1) * KC);
        }
        #pragma unroll
        for (int kk = 0; kk < KC; kk++) {
            float4 a = *(const float4*)&As[buf][kk][m0];
            float4 b = *(const float4*)&Ws[buf][kk][n0];
            acc[0][0] = fmaf(a.x, b.x, acc[0][0]);
            acc[0][1] = fmaf(a.x, b.y, acc[0][1]);
            acc[0][2] = fmaf(a.x, b.z, acc[0][2]);
            acc[0][3] = fmaf(a.x, b.w, acc[0][3]);
            acc[1][0] = fmaf(a.y, b.x, acc[1][0]);
            acc[1][1] = fmaf(a.y, b.y, acc[1][1]);
            acc[1][2] = fmaf(a.y, b.z, acc[1][2]);
            acc[1][3] = fmaf(a.y, b.w, acc[1][3]);
            acc[2][0] = fmaf(a.z, b.x, acc[2][0]);
            acc[2][1] = fmaf(a.z, b.y, acc[2][1]);
            acc[2][2] = fmaf(a.z, b.z, acc[2][2]);
            acc[2][3] = fmaf(a.z, b.w, acc[2][3]);
            acc[3][0] = fmaf(a.w, b.x, acc[3][0]);
            acc[3][1] = fmaf(a.w, b.y, acc[3][1]);
            acc[3][2] = fmaf(a.w, b.z, acc[3][2]);
            acc[3][3] = fmaf(a.w, b.w, acc[3][3]);
        }
        if (c + 1 < NC) {                       // fill other buffer
            int nb = buf ^ 1;
            As[nb][lk + 0][lm] = ra.x; As[nb][lk + 1][lm] = ra.y;
            As[nb][lk + 2][lm] = ra.z; As[nb][lk + 3][lm] = ra.w;
            Ws[nb][lk + 0][lm] = rw.x; Ws[nb][lk + 1][lm] = rw.y;
            Ws[nb][lk + 2][lm] = rw.z; Ws[nb][lk + 3][lm] = rw.w;
        }
        __syncthreads();
    }

    #pragma unroll
    for (int i = 0; i < 4; i++) {
        float4 o; o.x = acc[i][0]; o.y = acc[i][1]; o.z = acc[i][2]; o.w = acc[i][3];
        *(float4*)&outp[(size_t)(m0 + i) * DIM + ntile * 64 + n0] = o;
    }
}

// ---------------------------------------------------------------------------
// Phase 1: kp splits (128) + qp splits (128) + w1_row_sum (16) = 272 blocks
// ---------------------------------------------------------------------------
__global__ __launch_bounds__(256) void phase1_kernel(
    const float* __restrict__ q, const float* __restrict__ Wq,
    const float* __restrict__ k, const float* __restrict__ Wk,
    const float* __restrict__ Wg)
{
    int bb = blockIdx.x;
    if (bb < 128) {
        gemm_split(k, Wk, DIM, g_kp_part[bb >> 4], bb & 15, bb >> 4);
    } else if (bb < 256) {
        int b2 = bb - 128;
        gemm_split(q, Wq, DIM, g_qp_part[b2 >> 4], b2 & 15, b2 >> 4);
    } else {
        int warp = threadIdx.x >> 5, lane = threadIdx.x & 31;
        int base = (bb - 256) * 64;
        #pragma unroll
        for (int it = 0; it < 8; it++) {
            int row = base + it * 8 + warp;
            const float* p = Wg + (size_t)row * (2 * DIM);
            float s = 0.f;
            #pragma unroll 8
            for (int t = 0; t < DIM / 32; t++) s += p[lane + 32 * t];
            #pragma unroll
            for (int o = 16; o > 0; o >>= 1) s += __shfl_xor_sync(0xffffffffu, s, o);
            if (lane == 0) g_w1s[row] = s;
        }
    }
}

// ---------------------------------------------------------------------------
// Phase 2: reduce split buffers -> final qp/kp (+bias). 128 blocks x 256 thr.
// blocks 0..63: qp (16384 float4s), blocks 64..127: kp.
// ---------------------------------------------------------------------------
__global__ __launch_bounds__(256) void reduce_kernel(
    const float* __restrict__ bq, const float* __restrict__ bk)
{
    int bb = blockIdx.x;
    bool is_k = bb >= 64;
    int t = (is_k ? bb - 64 : bb) * 256 + threadIdx.x;   // float4 index
    int n4 = t & 255;

    const float4* bias4 = (const float4*)(is_k ? bk : bq);
    float4 s = bias4[n4];
    const float (*part)[BATCH * DIM] = is_k ? g_kp_part : g_qp_part;
    #pragma unroll
    for (int sp = 0; sp < SPLITS; sp++) {
        float4 v = ((const float4*)part[sp])[t];
        s.x += v.x; s.y += v.y; s.z += v.z; s.w += v.w;
    }
    ((float4*)(is_k ? g_kp : g_qp))[t] = s;
}

// ---------------------------------------------------------------------------
// Phase 3: g2 partials = kp_final @ W2.T   (bg folded in attn preload)
// ---------------------------------------------------------------------------
__global__ __launch_bounds__(256) void g2_kernel(const float* __restrict__ Wg)
{
    int bb = blockIdx.x;
    gemm_split(g_kp, Wg + DIM, 2 * DIM, g_g2_part[bb >> 4], bb & 15, bb >> 4);
}

// ---------------------------------------------------------------------------
// Fused gate + scores + softmax (validated in R4: rel_err 4.1e-7).
// grid (32, 64). 256 threads = 4 groups of 64 lanes, one row per group,
// 16 j-elems/lane in regs. g2 = sum of 8 split buffers + bg at preload.
// sigmoid(x)=0.5+0.5*tanh(x/2); inner tanh via degree-7 odd poly (arg<0.5)
// -> 2 MUFU/elem. No max-subtraction (|score*gate| <~ 5, fp32-safe).
// ---------------------------------------------------------------------------
__device__ __forceinline__ float elem_(float qp, float w1s_h, float g2_h,
                                       float kp_sh, float& sum)
{
    float qkh = qp * kp_sh;                      // 0.5*log2e*score
    float gph = fmaf(qp, w1s_h, g2_h);           // 0.5*gate_pre
    float t1  = tanhf_(gph);                     // tanh(gate_pre/2)
    float v   = fmaf(0.25f, t1, 0.25f);          // s1/2 in (0, 0.5)
    float w   = v * v;
    float p   = fmaf(-0.05396825f, w, 0.13333333f);
    p = fmaf(p, w, -0.33333333f);
    p = fmaf(p, w, 1.0f);
    float t2  = v * p;                           // tanh(s1/2)
    float e   = ex2f_(fmaf(qkh, t2, qkh));       // exp2(log2e*score*gate)
    sum += e;
    return e;
}

__global__ __launch_bounds__(256) void attn_kernel(float* __restrict__ out,
                                                   const float* __restrict__ bg)
{
    int tid   = threadIdx.x;
    int group = tid >> 6;
    int gl    = tid & 63;
    int warp  = tid >> 5;
    int lane  = tid & 31;
    int b     = blockIdx.y;

    const float4* kp4  = (const float4*)(g_kp + (size_t)b * DIM);
    const float4* w1s4 = (const float4*)g_w1s;
    const float4* bg4  = (const float4*)bg;

    const float KS = 0.5f * LOG2E;
    float4 kps[4], g2s[4], w1ss[4];
    #pragma unroll
    for (int t = 0; t < 4; t++) {
        int idx = t * 64 + gl;
        float4 kv = kp4[idx];
        kps[t].x = kv.x * KS;   kps[t].y = kv.y * KS;
        kps[t].z = kv.z * KS;   kps[t].w = kv.w * KS;
        float4 gv = bg4[idx];
        #pragma unroll
        for (int sp = 0; sp < SPLITS; sp++) {
            float4 pv = ((const float4*)(g_g2_part[sp] + (size_t)b * DIM))[idx];
            gv.x += pv.x; gv.y += pv.y; gv.z += pv.z; gv.w += pv.w;
        }
        g2s[t].x = gv.x * 0.5f; g2s[t].y = gv.y * 0.5f;
        g2s[t].z = gv.z * 0.5f; g2s[t].w = gv.w * 0.5f;
        float4 wv = w1s4[idx];
        w1ss[t].x = wv.x * 0.5f; w1ss[t].y = wv.y * 0.5f;
        w1ss[t].z = wv.z * 0.5f; w1ss[t].w = wv.w * 0.5f;
    }

    __shared__ float s_part[2][8];

    const float* qp_row = g_qp + (size_t)b * DIM;
    int i0 = blockIdx.x * 32 + group;

    for (int r = 0; r < 8; r++) {
        int i = i0 + r * 4;
        float qp = __ldg(qp_row + i);
        float sum = 0.f;
        float4 ev[4];
        #pragma unroll
        for (int t = 0; t < 4; t++) {
            ev[t].x = elem_(qp, w1ss[t].x, g2s[t].x, kps[t].x, sum);
            ev[t].y = elem_(qp, w1ss[t].y, g2s[t].y, kps[t].y, sum);
            ev[t].z = elem_(qp, w1ss[t].z, g2s[t].z, kps[t].z, sum);
            ev[t].w = elem_(qp, w1ss[t].w, g2s[t].w, kps[t].w, sum);
        }
        #pragma unroll
        for (int o = 16; o > 0; o >>= 1) sum += __shfl_xor_sync(0xffffffffu, sum, o);
        if (lane == 0) s_part[r & 1][warp] = sum;
        __syncthreads();
        float tot  = s_part[r & 1][group * 2] + s_part[r & 1][group * 2 + 1];
        float rinv = rcpf_(tot);

        float4* o4 = (float4*)out + (size_t)(b * DIM + i) * (DIM / 4);
        #pragma unroll
        for (int t = 0; t < 4; t++) {
            float4 o;
            o.x = ev[t].x * rinv; o.y = ev[t].y * rinv;
            o.z = ev[t].z * rinv; o.w = ev[t].w * rinv;
            __stcs(&o4[t * 64 + gl], o);
        }
    }
}

// ---------------------------------------------------------------------------
extern "C" void kernel_launch(void* const* d_in, const int* in_sizes, int n_in,
                              void* d_out, int out_size)
{
    const float* q  = (const float*)d_in[0];
    const float* k  = (const float*)d_in[1];
    // d_in[2] = v : unused by the reference math
    const float* Wq = (const float*)d_in[3];
    const float* bq = (const float*)d_in[4];
    const float* Wk = (const float*)d_in[5];
    const float* bk = (const float*)d_in[6];
    const float* Wg = (const float*)d_in[7];
    const float* bg = (const float*)d_in[8];
    float* out = (float*)d_out;

    phase1_kernel<<<272, 256>>>(q, Wq, k, Wk, Wg);
    reduce_kernel<<<128, 256>>>(bq, bk);
    g2_kernel    <<<128, 256>>>(Wg);
    attn_kernel  <<<dim3(32, 64), 256>>>(out, bg);
}

// round 16
// speedup vs baseline: 1.1423x; 1.1096x over previous
#include <cuda_runtime.h>

#define DIM    1024
#define BATCH  64
#define LOG2E  1.44269504f
#define SPLITS 8
#define KSEG   (DIM / SPLITS)
#define KC     16
#define NC     (KSEG / KC)

typedef unsigned long long ull;

// ---- scratch (device globals: no allocations allowed) ----
__device__ __align__(16) float g_qp_part[SPLITS][BATCH * DIM];
__device__ __align__(16) float g_kp_part[SPLITS][BATCH * DIM];
__device__ __align__(16) float g_g2_part[SPLITS][BATCH * DIM];
__device__ __align__(16) float g_qp[BATCH * DIM];
__device__ __align__(16) float g_kp[BATCH * DIM];
__device__ __align__(16) float g_w1s[DIM];

__device__ __forceinline__ float ex2f_(float x) {
    float y; asm("ex2.approx.ftz.f32 %0, %1;" : "=f"(y) : "f"(x)); return y;
}
__device__ __forceinline__ float rcpf_(float x) {
    float y; asm("rcp.approx.ftz.f32 %0, %1;" : "=f"(y) : "f"(x)); return y;
}
__device__ __forceinline__ float tanhf_(float x) {
    float y; asm("tanh.approx.f32 %0, %1;" : "=f"(y) : "f"(x)); return y;
}

// packed f32x2 helpers
#define PK2(d, lo, hi)  asm("mov.b64 %0, {%1, %2};" : "=l"(d) : "f"(lo), "f"(hi))
#define UPK2(lo, hi, s) asm("mov.b64 {%0, %1}, %2;" : "=f"(lo), "=f"(hi) : "l"(s))
#define MUL2(d, a, b)   asm("mul.rn.f32x2 %0, %1, %2;" : "=l"(d) : "l"(a), "l"(b))
#define ADD2(d, a, b)   asm("add.rn.f32x2 %0, %1, %2;" : "=l"(d) : "l"(a), "l"(b))
#define FMA2(d, a, b, c) asm("fma.rn.f32x2 %0, %1, %2, %3;" : "=l"(d) : "l"(a), "l"(b), "l"(c))

// ---------------------------------------------------------------------------
// Split-K smem-tiled GEMM partial (validated R14: prologue 31.6 -> ~15 us)
// ---------------------------------------------------------------------------
__device__ __forceinline__ void gemm_split(const float* __restrict__ A,
                                           const float* __restrict__ W, int ldw,
                                           float* __restrict__ outp,
                                           int ntile, int split)
{
    __shared__ float As[2][KC][68];
    __shared__ float Ws[2][KC][68];

    int tid = threadIdx.x;
    int ty = tid >> 4, tx = tid & 15;
    int m0 = ty * 4,   n0 = tx * 4;
    int lm = tid >> 2, lk = (tid & 3) * 4;

    int kbase = split * KSEG;
    const float* aptr = A + (size_t)lm * DIM + kbase + lk;
    const float* wptr = W + (size_t)(ntile * 64 + lm) * ldw + kbase + lk;

    float4 ra = *(const float4*)aptr;
    float4 rw = *(const float4*)wptr;

    As[0][lk + 0][lm] = ra.x; As[0][lk + 1][lm] = ra.y;
    As[0][lk + 2][lm] = ra.z; As[0][lk + 3][lm] = ra.w;
    Ws[0][lk + 0][lm] = rw.x; Ws[0][lk + 1][lm] = rw.y;
    Ws[0][lk + 2][lm] = rw.z; Ws[0][lk + 3][lm] = rw.w;
    __syncthreads();

    float acc[4][4];
    #pragma unroll
    for (int i = 0; i < 4; i++)
        #pragma unroll
        for (int j = 0; j < 4; j++) acc[i][j] = 0.f;

    #pragma unroll 1
    for (int c = 0; c < NC; c++) {
        int buf = c & 1;
        if (c + 1 < NC) {
            ra = *(const float4*)(aptr + (c + 1) * KC);
            rw = *(const float4*)(wptr + (c + 1) * KC);
        }
        #pragma unroll
        for (int kk = 0; kk < KC; kk++) {
            float4 a = *(const float4*)&As[buf][kk][m0];
            float4 b = *(const float4*)&Ws[buf][kk][n0];
            acc[0][0] = fmaf(a.x, b.x, acc[0][0]);
            acc[0][1] = fmaf(a.x, b.y, acc[0][1]);
            acc[0][2] = fmaf(a.x, b.z, acc[0][2]);
            acc[0][3] = fmaf(a.x, b.w, acc[0][3]);
            acc[1][0] = fmaf(a.y, b.x, acc[1][0]);
            acc[1][1] = fmaf(a.y, b.y, acc[1][1]);
            acc[1][2] = fmaf(a.y, b.z, acc[1][2]);
            acc[1][3] = fmaf(a.y, b.w, acc[1][3]);
            acc[2][0] = fmaf(a.z, b.x, acc[2][0]);
            acc[2][1] = fmaf(a.z, b.y, acc[2][1]);
            acc[2][2] = fmaf(a.z, b.z, acc[2][2]);
            acc[2][3] = fmaf(a.z, b.w, acc[2][3]);
            acc[3][0] = fmaf(a.w, b.x, acc[3][0]);
            acc[3][1] = fmaf(a.w, b.y, acc[3][1]);
            acc[3][2] = fmaf(a.w, b.z, acc[3][2]);
            acc[3][3] = fmaf(a.w, b.w, acc[3][3]);
        }
        if (c + 1 < NC) {
            int nb = buf ^ 1;
            As[nb][lk + 0][lm] = ra.x; As[nb][lk + 1][lm] = ra.y;
            As[nb][lk + 2][lm] = ra.z; As[nb][lk + 3][lm] = ra.w;
            Ws[nb][lk + 0][lm] = rw.x; Ws[nb][lk + 1][lm] = rw.y;
            Ws[nb][lk + 2][lm] = rw.z; Ws[nb][lk + 3][lm] = rw.w;
        }
        __syncthreads();
    }

    #pragma unroll
    for (int i = 0; i < 4; i++) {
        float4 o; o.x = acc[i][0]; o.y = acc[i][1]; o.z = acc[i][2]; o.w = acc[i][3];
        *(float4*)&outp[(size_t)(m0 + i) * DIM + ntile * 64 + n0] = o;
    }
}

__global__ __launch_bounds__(256) void phase1_kernel(
    const float* __restrict__ q, const float* __restrict__ Wq,
    const float* __restrict__ k, const float* __restrict__ Wk,
    const float* __restrict__ Wg)
{
    int bb = blockIdx.x;
    if (bb < 128) {
        gemm_split(k, Wk, DIM, g_kp_part[bb >> 4], bb & 15, bb >> 4);
    } else if (bb < 256) {
        int b2 = bb - 128;
        gemm_split(q, Wq, DIM, g_qp_part[b2 >> 4], b2 & 15, b2 >> 4);
    } else {
        int warp = threadIdx.x >> 5, lane = threadIdx.x & 31;
        int base = (bb - 256) * 64;
        #pragma unroll
        for (int it = 0; it < 8; it++) {
            int row = base + it * 8 + warp;
            const float* p = Wg + (size_t)row * (2 * DIM);
            float s = 0.f;
            #pragma unroll 8
            for (int t = 0; t < DIM / 32; t++) s += p[lane + 32 * t];
            #pragma unroll
            for (int o = 16; o > 0; o >>= 1) s += __shfl_xor_sync(0xffffffffu, s, o);
            if (lane == 0) g_w1s[row] = s;
        }
    }
}

__global__ __launch_bounds__(256) void reduce_kernel(
    const float* __restrict__ bq, const float* __restrict__ bk)
{
    int bb = blockIdx.x;
    bool is_k = bb >= 64;
    int t = (is_k ? bb - 64 : bb) * 256 + threadIdx.x;
    int n4 = t & 255;

    const float4* bias4 = (const float4*)(is_k ? bk : bq);
    float4 s = bias4[n4];
    const float (*part)[BATCH * DIM] = is_k ? g_kp_part : g_qp_part;
    #pragma unroll
    for (int sp = 0; sp < SPLITS; sp++) {
        float4 v = ((const float4*)part[sp])[t];
        s.x += v.x; s.y += v.y; s.z += v.z; s.w += v.w;
    }
    ((float4*)(is_k ? g_kp : g_qp))[t] = s;
}

__global__ __launch_bounds__(256) void g2_kernel(const float* __restrict__ Wg)
{
    int bb = blockIdx.x;
    gemm_split(g_kp, Wg + DIM, 2 * DIM, g_g2_part[bb >> 4], bb & 15, bb >> 4);
}

// ---------------------------------------------------------------------------
// Fused gate + scores + softmax, PACKED f32x2 math.
// grid (64, 64): blockIdx.y = batch, blockIdx.x = 16-row i-tile.
// 256 threads = 2 groups of 128 lanes; each group owns a row (4 warps/row),
// 8 j-elems (4 f32x2 pairs) per lane in regs -> ~60 regs, 4 blocks/SM.
// Per pair: 2 scalar MUFU (tanh, ex2) + ~11 packed fma-pipe ops;
// pack/unpack movs ride the idle ALU pipe.
// Math identical to R14-validated version (rel_err 4.1e-7).
// ---------------------------------------------------------------------------
__device__ __forceinline__ ull pair_(ull qp2, ull w1s2, ull g2s2, ull kp2,
                                     ull Q2, ull C7, ull C5, ull C3, ull ONE2,
                                     ull& sum2)
{
    ull qk2, gp2, v2, w2, p2, t2p, ea2, e2;
    MUL2(qk2, qp2, kp2);                 // 0.5*log2e*score (x2)
    FMA2(gp2, qp2, w1s2, g2s2);          // 0.5*gate_pre (x2)
    float g0, g1; UPK2(g0, g1, gp2);
    float t0 = tanhf_(g0), t1 = tanhf_(g1);
    PK2(t2p, t0, t1);
    FMA2(v2, Q2, t2p, Q2);               // s1/2 in (0,0.5) (x2)
    MUL2(w2, v2, v2);
    FMA2(p2, C7, w2, C5);
    FMA2(p2, p2, w2, C3);
    FMA2(p2, p2, w2, ONE2);
    MUL2(t2p, v2, p2);                   // tanh(s1/2) (x2)
    FMA2(ea2, qk2, t2p, qk2);            // log2e*score*gate (x2)
    float a0, a1; UPK2(a0, a1, ea2);
    float e0 = ex2f_(a0), e1 = ex2f_(a1);
    PK2(e2, e0, e1);
    ADD2(sum2, sum2, e2);
    return e2;
}

__global__ __launch_bounds__(256) void attn_kernel(float* __restrict__ out,
                                                   const float* __restrict__ bg)
{
    int tid   = threadIdx.x;
    int group = tid >> 7;      // 0..1
    int gl    = tid & 127;     // lane within 128-lane group
    int warp  = tid >> 5;      // 0..7
    int lane  = tid & 31;
    int b     = blockIdx.y;

    const float4* kp4  = (const float4*)(g_kp + (size_t)b * DIM);
    const float4* w1s4 = (const float4*)g_w1s;
    const float4* bg4  = (const float4*)bg;

    ull Q2, C7, C5, C3, ONE2, KS2, HALF2;
    { const float ks = 0.5f * LOG2E;
      PK2(KS2, ks, ks); PK2(HALF2, 0.5f, 0.5f);
      PK2(Q2, 0.25f, 0.25f);
      PK2(C7, -0.05396825f, -0.05396825f);
      PK2(C5, 0.13333333f, 0.13333333f);
      PK2(C3, -0.33333333f, -0.33333333f);
      PK2(ONE2, 1.0f, 1.0f); }

    ull kps2[4], g2s2[4], w1ss2[4];
    #pragma unroll
    for (int t = 0; t < 2; t++) {
        int idx = t * 128 + gl;
        float4 kv = kp4[idx];
        ull pa, pb;
        PK2(pa, kv.x, kv.y); PK2(pb, kv.z, kv.w);
        MUL2(kps2[2*t],   pa, KS2);
        MUL2(kps2[2*t+1], pb, KS2);

        float4 gv = bg4[idx];
        #pragma unroll
        for (int sp = 0; sp < SPLITS; sp++) {
            float4 pv = ((const float4*)(g_g2_part[sp] + (size_t)b * DIM))[idx];
            gv.x += pv.x; gv.y += pv.y; gv.z += pv.z; gv.w += pv.w;
        }
        PK2(pa, gv.x, gv.y); PK2(pb, gv.z, gv.w);
        MUL2(g2s2[2*t],   pa, HALF2);
        MUL2(g2s2[2*t+1], pb, HALF2);

        float4 wv = w1s4[idx];
        PK2(pa, wv.x, wv.y); PK2(pb, wv.z, wv.w);
        MUL2(w1ss2[2*t],   pa, HALF2);
        MUL2(w1ss2[2*t+1], pb, HALF2);
    }

    __shared__ float s_part[2][8];

    const float* qp_row = g_qp + (size_t)b * DIM;
    int i0 = blockIdx.x * 16 + group;

    for (int r = 0; r < 8; r++) {
        int i = i0 + r * 2;
        float qp = __ldg(qp_row + i);
        ull qp2; PK2(qp2, qp, qp);
        ull sum2 = 0ull;
        ull ev2[4];
        #pragma unroll
        for (int t = 0; t < 4; t++)
            ev2[t] = pair_(qp2, w1ss2[t], g2s2[t], kps2[t],
                           Q2, C7, C5, C3, ONE2, sum2);

        float s0, s1; UPK2(s0, s1, sum2);
        float sum = s0 + s1;
        #pragma unroll
        for (int o = 16; o > 0; o >>= 1) sum += __shfl_xor_sync(0xffffffffu, sum, o);
        if (lane == 0) s_part[r & 1][warp] = sum;
        __syncthreads();
        float tot = s_part[r & 1][group * 4 + 0] + s_part[r & 1][group * 4 + 1]
                  + s_part[r & 1][group * 4 + 2] + s_part[r & 1][group * 4 + 3];
        float rinv = rcpf_(tot);
        ull rinv2; PK2(rinv2, rinv, rinv);

        float4* o4 = (float4*)out + (size_t)(b * DIM + i) * (DIM / 4);
        #pragma unroll
        for (int t = 0; t < 2; t++) {
            ull oa, ob;
            MUL2(oa, ev2[2*t],   rinv2);
            MUL2(ob, ev2[2*t+1], rinv2);
            float4 o;
            UPK2(o.x, o.y, oa);
            UPK2(o.z, o.w, ob);
            __stcs(&o4[t * 128 + gl], o);
        }
    }
}

// ---------------------------------------------------------------------------
extern "C" void kernel_launch(void* const* d_in, const int* in_sizes, int n_in,
                              void* d_out, int out_size)
{
    const float* q  = (const float*)d_in[0];
    const float* k  = (const float*)d_in[1];
    // d_in[2] = v : unused by the reference math
    const float* Wq = (const float*)d_in[3];
    const float* bq = (const float*)d_in[4];
    const float* Wk = (const float*)d_in[5];
    const float* bk = (const float*)d_in[6];
    const float* Wg = (const float*)d_in[7];
    const float* bg = (const float*)d_in[8];
    float* out = (float*)d_out;

    phase1_kernel<<<272, 256>>>(q, Wq, k, Wk, Wg);
    reduce_kernel<<<128, 256>>>(bq, bk);
    g2_kernel    <<<128, 256>>>(Wg);
    attn_kernel  <<<dim3(64, 64), 256>>>(out, bg);
}